// round 1
// baseline (speedup 1.0000x reference)
#include <cuda_runtime.h>

#define K_IMG 27

// Scratch (allocation-free per harness rules). Sized with margin for M=8, N=400.
__device__ float4 g_wrapped[8192];      // per atom: wrapped xyz, packed wrap_off in .w
__device__ float4 g_shift[512];         // per (m,k): image_k @ cell_m

__global__ void prep_kernel(const float* __restrict__ coords,
                            const float* __restrict__ cellg,
                            int M, int N)
{
    int t = blockIdx.x * blockDim.x + threadIdx.x;
    int atoms = M * N;
    if (t < atoms) {
        int m = t / N;
        const float* A = cellg + m * 9;
        float a00=A[0],a01=A[1],a02=A[2],a10=A[3],a11=A[4],a12=A[5],a20=A[6],a21=A[7],a22=A[8];
        // 3x3 inverse via adjugate
        float c00 = a11*a22 - a12*a21;
        float c01 = a12*a20 - a10*a22;
        float c02 = a10*a21 - a11*a20;
        float invdet = 1.0f / (a00*c00 + a01*c01 + a02*c02);
        float i00 = c00*invdet;
        float i01 = (a02*a21 - a01*a22)*invdet;
        float i02 = (a01*a12 - a02*a11)*invdet;
        float i10 = c01*invdet;
        float i11 = (a00*a22 - a02*a20)*invdet;
        float i12 = (a02*a10 - a00*a12)*invdet;
        float i20 = c02*invdet;
        float i21 = (a01*a20 - a00*a21)*invdet;
        float i22 = (a00*a11 - a01*a10)*invdet;

        const float* c = coords + (long long)t * 3;
        float x = c[0], y = c[1], z = c[2];
        // proj[e] = sum_d coord[d] * inv[d][e]
        float p0 = x*i00 + y*i10 + z*i20;
        float p1 = x*i01 + y*i11 + z*i21;
        float p2 = x*i02 + y*i12 + z*i22;
        float w0 = floorf(p0), w1 = floorf(p1), w2 = floorf(p2);
        // wrapped[d] = coord[d] - sum_e wo[e] * cell[e][d]
        float wx = x - (w0*a00 + w1*a10 + w2*a20);
        float wy = y - (w0*a01 + w1*a11 + w2*a21);
        float wz = z - (w0*a02 + w1*a12 + w2*a22);
        int pw = (((int)w0 + 128) << 16) | (((int)w1 + 128) << 8) | ((int)w2 + 128);
        g_wrapped[t] = make_float4(wx, wy, wz, __int_as_float(pw));
    } else if (t < atoms + M * K_IMG) {
        int s = t - atoms;
        int m = s / K_IMG, k = s % K_IMG;
        const float* A = cellg + m * 9;
        float fx = (float)(k / 9 - 1);
        float fy = (float)((k / 3) % 3 - 1);
        float fz = (float)(k % 3 - 1);
        // shift[d] = sum_c image[c] * cell[c][d]
        float sx = fx*A[0] + fy*A[3] + fz*A[6];
        float sy = fx*A[1] + fy*A[4] + fz*A[7];
        float sz = fx*A[2] + fy*A[5] + fz*A[8];
        g_shift[m * K_IMG + k] = make_float4(sx, sy, sz, 0.0f);
    }
}

__global__ void __launch_bounds__(256)
main_kernel(float* __restrict__ out, int M, int N, int NV4,
            long long base_pc, long long base_mask, long long base_off)
{
    int id = blockIdx.x * blockDim.x + threadIdx.x;
    int total = M * K_IMG * N * NV4;
    if (id >= total) return;

    int j4 = id % NV4;
    int t  = id / NV4;
    int i  = t % N;  t /= N;
    int k  = t % K_IMG;
    int m  = t / K_IMG;

    float4 ai = g_wrapped[m * N + i];
    int woi = __float_as_int(ai.w);
    float4 sh = g_shift[m * K_IMG + k];
    int ix = k / 9 - 1, iy = (k / 3) % 3 - 1, iz = k % 3 - 1;
    bool zk = (k == 13);   // the (0,0,0) image in ij-meshgrid order

    float dist4[4], pc[12], mk[4], off[4];
    int jb = j4 * 4;
    const float4* wj = &g_wrapped[m * N + jb];

    #pragma unroll
    for (int jj = 0; jj < 4; jj++) {
        float4 aj = wj[jj];
        float px = ai.x - aj.x + sh.x;
        float py = ai.y - aj.y + sh.y;
        float pz = ai.z - aj.z + sh.z;
        float d2 = px*px + py*py + pz*pz;
        bool msk = (d2 < 36.0f) && !(zk && (i == jb + jj));
        dist4[jj]    = msk ? sqrtf(d2) : 0.0f;
        pc[jj*3 + 0] = msk ? px : 0.0f;
        pc[jj*3 + 1] = msk ? py : 0.0f;
        pc[jj*3 + 2] = msk ? pz : 0.0f;
        mk[jj]       = msk ? 1.0f : 0.0f;

        int woj = __float_as_int(aj.w);
        int dwx = ((woi >> 16) & 0xff) - ((woj >> 16) & 0xff);
        int dwy = ((woi >>  8) & 0xff) - ((woj >>  8) & 0xff);
        int dwz = ( woi        & 0xff) - ( woj        & 0xff);
        int ox = ix - dwx + 1;
        int oy = iy - dwy + 1;
        int oz = iz - dwz + 1;
        off[jj] = (float)(oz + 3 * (oy + 3 * ox));
    }

    long long row = (long long)((m * K_IMG + k) * N + i) * (long long)N;
    long long e = row + jb;

    *(float4*)(out + e) = make_float4(dist4[0], dist4[1], dist4[2], dist4[3]);

    float* po = out + base_pc + e * 3;
    ((float4*)po)[0] = make_float4(pc[0],  pc[1],  pc[2],  pc[3]);
    ((float4*)po)[1] = make_float4(pc[4],  pc[5],  pc[6],  pc[7]);
    ((float4*)po)[2] = make_float4(pc[8],  pc[9],  pc[10], pc[11]);

    *(float4*)(out + base_mask + e) = make_float4(mk[0], mk[1], mk[2], mk[3]);
    *(float4*)(out + base_off  + e) = make_float4(off[0], off[1], off[2], off[3]);
}

extern "C" void kernel_launch(void* const* d_in, const int* in_sizes, int n_in,
                              void* d_out, int out_size)
{
    const float* coords = (const float*)d_in[0];
    const float* cell   = (const float*)d_in[1];
    int M = in_sizes[1] / 9;
    int N = in_sizes[0] / (3 * M);
    int NV4 = N / 4;

    long long MKNN = (long long)M * K_IMG * N * N;

    int prepT = M * N + M * K_IMG;
    prep_kernel<<<(prepT + 255) / 256, 256>>>(coords, cell, M, N);

    int total = M * K_IMG * N * NV4;
    main_kernel<<<(total + 255) / 256, 256>>>((float*)d_out, M, N, NV4,
                                              MKNN, 4 * MKNN, 5 * MKNN);
}

// round 3
// speedup vs baseline: 1.2178x; 1.2178x over previous
#include <cuda_runtime.h>
#include <cstdint>

#define K_IMG 27
#define PAIRS_PER_BLOCK 1024   // 256 threads x 4 j's

__device__ float4 g_wrapped[8192];      // per atom: wrapped xyz, packed wrap_off in .w
__device__ float4 g_shift[512];         // per (m,k): image_k @ cell_m

__global__ void prep_kernel(const float* __restrict__ coords,
                            const float* __restrict__ cellg,
                            int M, int N)
{
    int t = blockIdx.x * blockDim.x + threadIdx.x;
    int atoms = M * N;
    if (t < atoms) {
        int m = t / N;
        const float* A = cellg + m * 9;
        float a00=A[0],a01=A[1],a02=A[2],a10=A[3],a11=A[4],a12=A[5],a20=A[6],a21=A[7],a22=A[8];
        float c00 = a11*a22 - a12*a21;
        float c01 = a12*a20 - a10*a22;
        float c02 = a10*a21 - a11*a20;
        float invdet = 1.0f / (a00*c00 + a01*c01 + a02*c02);
        float i00 = c00*invdet;
        float i01 = (a02*a21 - a01*a22)*invdet;
        float i02 = (a01*a12 - a02*a11)*invdet;
        float i10 = c01*invdet;
        float i11 = (a00*a22 - a02*a20)*invdet;
        float i12 = (a02*a10 - a00*a12)*invdet;
        float i20 = c02*invdet;
        float i21 = (a01*a20 - a00*a21)*invdet;
        float i22 = (a00*a11 - a01*a10)*invdet;

        const float* c = coords + (long long)t * 3;
        float x = c[0], y = c[1], z = c[2];
        float p0 = x*i00 + y*i10 + z*i20;
        float p1 = x*i01 + y*i11 + z*i21;
        float p2 = x*i02 + y*i12 + z*i22;
        float w0 = floorf(p0), w1 = floorf(p1), w2 = floorf(p2);
        float wx = x - (w0*a00 + w1*a10 + w2*a20);
        float wy = y - (w0*a01 + w1*a11 + w2*a21);
        float wz = z - (w0*a02 + w1*a12 + w2*a22);
        int pw = (((int)w0 + 128) << 16) | (((int)w1 + 128) << 8) | ((int)w2 + 128);
        g_wrapped[t] = make_float4(wx, wy, wz, __int_as_float(pw));
    } else if (t < atoms + M * K_IMG) {
        int s = t - atoms;
        int m = s / K_IMG, k = s % K_IMG;
        const float* A = cellg + m * 9;
        float fx = (float)(k / 9 - 1);
        float fy = (float)((k / 3) % 3 - 1);
        float fz = (float)(k % 3 - 1);
        float sx = fx*A[0] + fy*A[3] + fz*A[6];
        float sy = fx*A[1] + fy*A[4] + fz*A[7];
        float sz = fx*A[2] + fy*A[5] + fz*A[8];
        g_shift[m * K_IMG + k] = make_float4(sx, sy, sz, 0.0f);
    }
}

__device__ __forceinline__ uint32_t smem_u32(const void* p) {
    uint32_t a;
    asm("{ .reg .u64 t; cvta.to.shared.u64 t, %1; cvt.u32.u64 %0, t; }" : "=r"(a) : "l"(p));
    return a;
}

__global__ void __launch_bounds__(256)
main_kernel(float* __restrict__ out, int M, int N, int NV4,
            long long base_pc, long long base_mask, long long base_off)
{
    __shared__ alignas(128) float s_dist[PAIRS_PER_BLOCK];
    __shared__ alignas(128) float s_pc[3 * PAIRS_PER_BLOCK];
    __shared__ alignas(128) float s_mask[PAIRS_PER_BLOCK];
    __shared__ alignas(128) float s_off[PAIRS_PER_BLOCK];

    int t = threadIdx.x;
    int q = blockIdx.x * 256 + t;        // global quad index (4 pairs per quad)

    // decode quad -> (m,k,i,j4). 4 | N so a quad never crosses a row boundary.
    int j4 = q % NV4;
    int r  = q / NV4;
    int i  = r % N;   r /= N;
    int k  = r % K_IMG;
    int m  = r / K_IMG;

    float4 ai = g_wrapped[m * N + i];
    int woi = __float_as_int(ai.w);
    float4 sh = g_shift[m * K_IMG + k];
    int ix = k / 9 - 1, iy = (k / 3) % 3 - 1, iz = k % 3 - 1;
    bool zk = (k == 13);   // (0,0,0) image in ij-meshgrid order

    int jb = j4 * 4;
    const float4* wj = &g_wrapped[m * N + jb];

    float dist4[4], pc[12], mk[4], off[4];

    #pragma unroll
    for (int jj = 0; jj < 4; jj++) {
        float4 aj = wj[jj];
        float px = ai.x - aj.x + sh.x;
        float py = ai.y - aj.y + sh.y;
        float pz = ai.z - aj.z + sh.z;
        float d2 = px*px + py*py + pz*pz;
        bool msk = (d2 < 36.0f) && !(zk && (i == jb + jj));
        dist4[jj]    = msk ? sqrtf(d2) : 0.0f;
        pc[jj*3 + 0] = msk ? px : 0.0f;
        pc[jj*3 + 1] = msk ? py : 0.0f;
        pc[jj*3 + 2] = msk ? pz : 0.0f;
        mk[jj]       = msk ? 1.0f : 0.0f;

        int woj = __float_as_int(aj.w);
        int dwx = ((woi >> 16) & 0xff) - ((woj >> 16) & 0xff);
        int dwy = ((woi >>  8) & 0xff) - ((woj >>  8) & 0xff);
        int dwz = ( woi        & 0xff) - ( woj        & 0xff);
        off[jj] = (float)((iz - dwz + 1) + 3 * ((iy - dwy + 1) + 3 * (ix - dwx + 1)));
    }

    // stage to smem (all STS.128, conflict-free)
    *(float4*)(s_dist + t * 4) = make_float4(dist4[0], dist4[1], dist4[2], dist4[3]);
    ((float4*)(s_pc + t * 12))[0] = make_float4(pc[0],  pc[1],  pc[2],  pc[3]);
    ((float4*)(s_pc + t * 12))[1] = make_float4(pc[4],  pc[5],  pc[6],  pc[7]);
    ((float4*)(s_pc + t * 12))[2] = make_float4(pc[8],  pc[9],  pc[10], pc[11]);
    *(float4*)(s_mask + t * 4) = make_float4(mk[0], mk[1], mk[2], mk[3]);
    *(float4*)(s_off  + t * 4) = make_float4(off[0], off[1], off[2], off[3]);

    __syncthreads();

    if (t == 0) {
        long long base_e = (long long)blockIdx.x * PAIRS_PER_BLOCK;
        asm volatile("fence.proxy.async.shared::cta;" ::: "memory");

        float* g_dist = out + base_e;
        float* g_pc   = out + base_pc   + base_e * 3;
        float* g_mask = out + base_mask + base_e;
        float* g_off  = out + base_off  + base_e;

        asm volatile("cp.async.bulk.global.shared::cta.bulk_group [%0], [%1], %2;"
                     :: "l"(g_dist), "r"(smem_u32(s_dist)), "r"((int)(PAIRS_PER_BLOCK * 4)) : "memory");
        asm volatile("cp.async.bulk.global.shared::cta.bulk_group [%0], [%1], %2;"
                     :: "l"(g_pc),   "r"(smem_u32(s_pc)),   "r"((int)(PAIRS_PER_BLOCK * 12)) : "memory");
        asm volatile("cp.async.bulk.global.shared::cta.bulk_group [%0], [%1], %2;"
                     :: "l"(g_mask), "r"(smem_u32(s_mask)), "r"((int)(PAIRS_PER_BLOCK * 4)) : "memory");
        asm volatile("cp.async.bulk.global.shared::cta.bulk_group [%0], [%1], %2;"
                     :: "l"(g_off),  "r"(smem_u32(s_off)),  "r"((int)(PAIRS_PER_BLOCK * 4)) : "memory");
        asm volatile("cp.async.bulk.commit_group;" ::: "memory");
        asm volatile("cp.async.bulk.wait_group.read 0;" ::: "memory");
    }
    __syncthreads();   // no thread exits (releasing smem) until TMA has read it
}

extern "C" void kernel_launch(void* const* d_in, const int* in_sizes, int n_in,
                              void* d_out, int out_size)
{
    const float* coords = (const float*)d_in[0];
    const float* cell   = (const float*)d_in[1];
    int M = in_sizes[1] / 9;
    int N = in_sizes[0] / (3 * M);
    int NV4 = N / 4;

    long long MKNN = (long long)M * K_IMG * N * N;

    int prepT = M * N + M * K_IMG;
    prep_kernel<<<(prepT + 255) / 256, 256>>>(coords, cell, M, N);

    long long total_quads = (long long)M * K_IMG * N * NV4;
    int blocks = (int)((total_quads + 255) / 256);
    main_kernel<<<blocks, 256>>>((float*)d_out, M, N, NV4,
                                 MKNN, 4 * MKNN, 5 * MKNN);
}

// round 4
// speedup vs baseline: 1.2384x; 1.0169x over previous
#include <cuda_runtime.h>
#include <cstdint>

#define K_IMG 27
#define TILE_PAIRS 1024            // 256 threads x 4 j's per tile
#define GRID_CTAS 592              // 4 * 148 SMs

__device__ float4 g_wrapped[8192];     // per atom: wrapped xyz, packed wrap_off in .w
__device__ float4 g_shift[512];        // per (m,k): image_k @ cell_m

__global__ void prep_kernel(const float* __restrict__ coords,
                            const float* __restrict__ cellg,
                            int M, int N)
{
    int t = blockIdx.x * blockDim.x + threadIdx.x;
    int atoms = M * N;
    if (t < atoms) {
        int m = t / N;
        const float* A = cellg + m * 9;
        float a00=A[0],a01=A[1],a02=A[2],a10=A[3],a11=A[4],a12=A[5],a20=A[6],a21=A[7],a22=A[8];
        float c00 = a11*a22 - a12*a21;
        float c01 = a12*a20 - a10*a22;
        float c02 = a10*a21 - a11*a20;
        float invdet = 1.0f / (a00*c00 + a01*c01 + a02*c02);
        float i00 = c00*invdet;
        float i01 = (a02*a21 - a01*a22)*invdet;
        float i02 = (a01*a12 - a02*a11)*invdet;
        float i10 = c01*invdet;
        float i11 = (a00*a22 - a02*a20)*invdet;
        float i12 = (a02*a10 - a00*a12)*invdet;
        float i20 = c02*invdet;
        float i21 = (a01*a20 - a00*a21)*invdet;
        float i22 = (a00*a11 - a01*a10)*invdet;

        const float* c = coords + (long long)t * 3;
        float x = c[0], y = c[1], z = c[2];
        float p0 = x*i00 + y*i10 + z*i20;
        float p1 = x*i01 + y*i11 + z*i21;
        float p2 = x*i02 + y*i12 + z*i22;
        float w0 = floorf(p0), w1 = floorf(p1), w2 = floorf(p2);
        float wx = x - (w0*a00 + w1*a10 + w2*a20);
        float wy = y - (w0*a01 + w1*a11 + w2*a21);
        float wz = z - (w0*a02 + w1*a12 + w2*a22);
        int pw = (((int)w0 + 128) << 16) | (((int)w1 + 128) << 8) | ((int)w2 + 128);
        g_wrapped[t] = make_float4(wx, wy, wz, __int_as_float(pw));
    } else if (t < atoms + M * K_IMG) {
        int s = t - atoms;
        int m = s / K_IMG, k = s % K_IMG;
        const float* A = cellg + m * 9;
        float fx = (float)(k / 9 - 1);
        float fy = (float)((k / 3) % 3 - 1);
        float fz = (float)(k % 3 - 1);
        float sx = fx*A[0] + fy*A[3] + fz*A[6];
        float sy = fx*A[1] + fy*A[4] + fz*A[7];
        float sz = fx*A[2] + fy*A[5] + fz*A[8];
        g_shift[m * K_IMG + k] = make_float4(sx, sy, sz, 0.0f);
    }
}

__device__ __forceinline__ uint32_t smem_u32(const void* p) {
    uint32_t a;
    asm("{ .reg .u64 t; cvta.to.shared.u64 t, %1; cvt.u32.u64 %0, t; }" : "=r"(a) : "l"(p));
    return a;
}

struct Tile {
    float dist[TILE_PAIRS];
    float pc[3 * TILE_PAIRS];
    float mask[TILE_PAIRS];
    float off[TILE_PAIRS];
};

__global__ void __launch_bounds__(256)
main_kernel(float* __restrict__ out, int M, int N, int NV4, int ntiles,
            long long base_pc, long long base_mask, long long base_off)
{
    __shared__ alignas(128) Tile s[2];   // 2 x 24 KB

    int t = threadIdx.x;
    int buf = 0;
    int iter = 0;

    for (int tile = blockIdx.x; tile < ntiles; tile += GRID_CTAS, buf ^= 1, iter++) {
        int q = tile * 256 + t;          // global quad index (4 pairs per quad)

        int j4 = q % NV4;
        int r  = q / NV4;
        int i  = r % N;   r /= N;
        int k  = r % K_IMG;
        int m  = r / K_IMG;

        float4 ai = g_wrapped[m * N + i];
        int woi = __float_as_int(ai.w);
        float4 sh = g_shift[m * K_IMG + k];
        int ix = k / 9 - 1, iy = (k / 3) % 3 - 1, iz = k % 3 - 1;
        bool zk = (k == 13);             // (0,0,0) image in ij-meshgrid order

        int jb = j4 * 4;
        const float4* wj = &g_wrapped[m * N + jb];

        float dist4[4], pc[12], mk[4], off[4];

        #pragma unroll
        for (int jj = 0; jj < 4; jj++) {
            float4 aj = wj[jj];
            float px = ai.x - aj.x + sh.x;
            float py = ai.y - aj.y + sh.y;
            float pz = ai.z - aj.z + sh.z;
            float d2 = px*px + py*py + pz*pz;
            bool msk = (d2 < 36.0f) && !(zk && (i == jb + jj));
            dist4[jj]    = msk ? sqrtf(d2) : 0.0f;
            pc[jj*3 + 0] = msk ? px : 0.0f;
            pc[jj*3 + 1] = msk ? py : 0.0f;
            pc[jj*3 + 2] = msk ? pz : 0.0f;
            mk[jj]       = msk ? 1.0f : 0.0f;

            int woj = __float_as_int(aj.w);
            int dwx = ((woi >> 16) & 0xff) - ((woj >> 16) & 0xff);
            int dwy = ((woi >>  8) & 0xff) - ((woj >>  8) & 0xff);
            int dwz = ( woi        & 0xff) - ( woj        & 0xff);
            off[jj] = (float)((iz - dwz + 1) + 3 * ((iy - dwy + 1) + 3 * (ix - dwx + 1)));
        }

        // Before overwriting this buffer, ensure the bulk group that read it
        // (issued 2 iterations ago) has completed its smem reads. With <=1
        // outstanding group allowed, only last iteration's group may be pending.
        if (iter >= 2) {
            if (t == 0)
                asm volatile("cp.async.bulk.wait_group.read 1;" ::: "memory");
            __syncthreads();
        }

        Tile& S = s[buf];
        *(float4*)(S.dist + t * 4) = make_float4(dist4[0], dist4[1], dist4[2], dist4[3]);
        ((float4*)(S.pc + t * 12))[0] = make_float4(pc[0],  pc[1],  pc[2],  pc[3]);
        ((float4*)(S.pc + t * 12))[1] = make_float4(pc[4],  pc[5],  pc[6],  pc[7]);
        ((float4*)(S.pc + t * 12))[2] = make_float4(pc[8],  pc[9],  pc[10], pc[11]);
        *(float4*)(S.mask + t * 4) = make_float4(mk[0], mk[1], mk[2], mk[3]);
        *(float4*)(S.off  + t * 4) = make_float4(off[0], off[1], off[2], off[3]);

        __syncthreads();

        if (t == 0) {
            long long base_e = (long long)tile * TILE_PAIRS;
            asm volatile("fence.proxy.async.shared::cta;" ::: "memory");

            float* g_dist = out + base_e;
            float* g_pc   = out + base_pc   + base_e * 3;
            float* g_mask = out + base_mask + base_e;
            float* g_off  = out + base_off  + base_e;

            asm volatile("cp.async.bulk.global.shared::cta.bulk_group [%0], [%1], %2;"
                         :: "l"(g_dist), "r"(smem_u32(S.dist)), "r"((int)(TILE_PAIRS * 4)) : "memory");
            asm volatile("cp.async.bulk.global.shared::cta.bulk_group [%0], [%1], %2;"
                         :: "l"(g_pc),   "r"(smem_u32(S.pc)),   "r"((int)(TILE_PAIRS * 12)) : "memory");
            asm volatile("cp.async.bulk.global.shared::cta.bulk_group [%0], [%1], %2;"
                         :: "l"(g_mask), "r"(smem_u32(S.mask)), "r"((int)(TILE_PAIRS * 4)) : "memory");
            asm volatile("cp.async.bulk.global.shared::cta.bulk_group [%0], [%1], %2;"
                         :: "l"(g_off),  "r"(smem_u32(S.off)),  "r"((int)(TILE_PAIRS * 4)) : "memory");
            asm volatile("cp.async.bulk.commit_group;" ::: "memory");
        }
        __syncthreads();   // all threads agree the group for this buffer is committed
    }

    // Drain all outstanding groups before CTA exit releases smem.
    if (t == 0)
        asm volatile("cp.async.bulk.wait_group.read 0;" ::: "memory");
    __syncthreads();
}

extern "C" void kernel_launch(void* const* d_in, const int* in_sizes, int n_in,
                              void* d_out, int out_size)
{
    const float* coords = (const float*)d_in[0];
    const float* cell   = (const float*)d_in[1];
    int M = in_sizes[1] / 9;
    int N = in_sizes[0] / (3 * M);
    int NV4 = N / 4;

    long long MKNN = (long long)M * K_IMG * N * N;

    int prepT = M * N + M * K_IMG;
    prep_kernel<<<(prepT + 255) / 256, 256>>>(coords, cell, M, N);

    long long total_quads = (long long)M * K_IMG * N * NV4;
    int ntiles = (int)((total_quads + 255) / 256);
    int blocks = ntiles < GRID_CTAS ? ntiles : GRID_CTAS;
    main_kernel<<<blocks, 256>>>((float*)d_out, M, N, NV4, ntiles,
                                 MKNN, 4 * MKNN, 5 * MKNN);
}